// round 6
// baseline (speedup 1.0000x reference)
#include <cuda_runtime.h>
#include <math.h>

#define BS 4
#define LEN 2048
#define CIN 32
#define COUT 32
#define HIDDIM 64
#define KTAP 8
#define PADL 7
#define NPOS (BS * LEN)
#define RDIM (CIN * HIDDIM)      // 2048
#define EPSV 1e-5f
#define NWB 8                     // positions / warps per block
#define THREADS 256
#define NBLK (NPOS / NWB)         // 1024
#define MSPITCH 34                // u64 pitch per channel

typedef unsigned long long u64;

__device__ double g_stats[2 * COUT];
__device__ int    g_sync;

// ---- register-pure packed helpers ----
#define FMA2(d, a, b, c) \
    asm("fma.rn.f32x2 %0, %1, %2, %3;" : "=l"(d) : "l"(a), "l"(b), "l"(c))

__device__ __forceinline__ u64 pack2(float x, float y) {
    u64 d; asm("mov.b64 %0, {%1, %2};" : "=l"(d) : "f"(x), "f"(y)); return d;
}
__device__ __forceinline__ u64 packdup(float x) {
    u64 d; asm("mov.b64 %0, {%1, %1};" : "=l"(d) : "f"(x)); return d;
}
__device__ __forceinline__ void unpack2(u64 v, float& x, float& y) {
    asm("mov.b64 {%0, %1}, %2;" : "=f"(x), "=f"(y) : "l"(v));
}

// mask dtype hedge (byte 1 nonzero <=> 1-byte storage; else 4-byte words)
__device__ __forceinline__ bool mask_at(const void* m, int idx, bool byte_mode) {
    if (byte_mode) return ((const unsigned char*)m)[idx] != 0;
    return ((const unsigned int*)m)[idx] != 0u;
}

struct SmemT {
    float W1s[CIN * HIDDIM];      // 8KB
    float b1s[HIDDIM];
    float b2s[CIN * COUT];        // 4KB
    float wsk[CIN * COUT];        // 4KB
    float bsk[COUT];
    float ff[NWB][CIN];           // 1KB
    float fs[NWB][CIN];           // 1KB
    float ssum[COUT], ssq[COUT];
    int   pflag[NWB];
    union alignas(16) {
        struct {
            float teu[NWB][CIN][KTAP];    // 8KB
            float hb[NWB][KTAP][HIDDIM];  // 16KB
        } a;
        float red[NWB][NWB][COUT];        // 8KB
    } u;                                  // = 24KB
    u64 Msu[NWB][CIN * MSPITCH];          // 68KB
};                                        // ~110.7KB -> 2 blocks/SM

__global__ __launch_bounds__(THREADS, 2)
void kfused(const float* __restrict__ times,
            const float* __restrict__ features,
            const void*  __restrict__ mask,
            const float* __restrict__ W1,
            const float* __restrict__ b1,
            const float* __restrict__ W2,
            const float* __restrict__ b2,
            const float* __restrict__ Wskip,
            const float* __restrict__ bskip,
            float* __restrict__ out) {
    extern __shared__ char smem_raw[];
    SmemT* s = (SmemT*)smem_raw;

    int tid  = threadIdx.x;
    int wid  = tid >> 5;
    int lane = tid & 31;

    // ---- stage constants ----
    for (int i = tid; i < CIN * HIDDIM; i += THREADS) s->W1s[i] = W1[i];
    for (int i = tid; i < CIN * COUT; i += THREADS) {
        s->b2s[i] = b2[i];
        s->wsk[i] = Wskip[i];
    }
    if (tid < HIDDIM) s->b1s[tid] = b1[tid];
    if (tid < COUT) {
        s->bsk[tid]  = bskip[tid];
        s->ssum[tid] = 0.0f;
        s->ssq[tid]  = 0.0f;
    }
    __syncthreads();

    // ================= phase A: build M row (warp per position) ============
    int p = blockIdx.x * NWB + wid;
    int b = p >> 11;
    int t = p & (LEN - 1);

    bool byte_mode = ((const unsigned char*)mask)[1] != 0;
    bool mask_t = mask_at(mask, p, byte_mode);
    float t_here = times[p];

    s->ff[wid][lane] = features[(size_t)p * CIN + lane];

    unsigned vmask = 0;
#pragma unroll
    for (int k = 0; k < KTAP; k++) {
        int idx = t - PADL + k;
        bool dm = mask_t && (idx >= 0);
        if (dm) dm = mask_at(mask, b * LEN + idx, byte_mode);
        if (dm) vmask |= (1u << k);
    }
    bool any = (vmask != 0);
    float fsum = 0.0f;

    if (any) {
        // --- te for all taps (lane = channel i) ---
        float inv_pos = __expf(-(float)(lane >> 1) * (9.210340371976184f / 16.0f));
        float phase   = (lane & 1) ? 1.5707963267948966f : 0.0f;
        float fk[KTAP];
#pragma unroll
        for (int k = 0; k < KTAP; k++) {
            int idx = t - PADL + k;
            float te = 0.0f;
            fk[k] = 0.0f;
            if ((vmask >> k) & 1) {
                float dt = t_here - times[b * LEN + idx];
                te = __sinf(dt * inv_pos + phase);
                fk[k] = features[(size_t)(b * LEN + idx) * CIN + lane];
            }
            s->u.a.teu[wid][lane][k] = te;
            fsum += fk[k];
        }
        __syncwarp();

        // --- h for all taps, i-outer (lane = j; also j+32) ---
        u64 hh[4][2];
#pragma unroll
        for (int k2 = 0; k2 < 4; k2++) {
            hh[k2][0] = packdup(s->b1s[lane]);
            hh[k2][1] = packdup(s->b1s[lane + 32]);
        }
#pragma unroll
        for (int i = 0; i < CIN; i++) {
            u64 w0 = packdup(s->W1s[i * HIDDIM + lane]);
            u64 w1 = packdup(s->W1s[i * HIDDIM + lane + 32]);
#pragma unroll
            for (int k2 = 0; k2 < 4; k2++) {
                u64 tp = *(const u64*)&s->u.a.teu[wid][i][2 * k2];  // bcast
                FMA2(hh[k2][0], tp, w0, hh[k2][0]);
                FMA2(hh[k2][1], tp, w1, hh[k2][1]);
            }
        }
#pragma unroll
        for (int k2 = 0; k2 < 4; k2++) {
            float a0, c0, a1, c1;
            unpack2(hh[k2][0], a0, c0);
            unpack2(hh[k2][1], a1, c1);
            s->u.a.hb[wid][2 * k2][lane]          = fmaxf(a0, 0.0f);
            s->u.a.hb[wid][2 * k2 + 1][lane]      = fmaxf(c0, 0.0f);
            s->u.a.hb[wid][2 * k2][lane + 32]     = fmaxf(a1, 0.0f);
            s->u.a.hb[wid][2 * k2 + 1][lane + 32] = fmaxf(c1, 0.0f);
        }
        __syncwarp();

        // --- M update (lane = channel) ---
        u64 Macc[32];
#pragma unroll
        for (int q = 0; q < 32; q++) Macc[q] = 0ull;
#pragma unroll
        for (int k = 0; k < KTAP; k++) {
            if (!((vmask >> k) & 1)) continue;     // warp-uniform
            u64 f2 = packdup(fk[k]);
            const ulonglong2* hp2 = (const ulonglong2*)&s->u.a.hb[wid][k][0];
#pragma unroll
            for (int q2 = 0; q2 < 16; q2++) {
                ulonglong2 hp = hp2[q2];           // broadcast LDS.128
                FMA2(Macc[2 * q2],     f2, hp.x, Macc[2 * q2]);
                FMA2(Macc[2 * q2 + 1], f2, hp.y, Macc[2 * q2 + 1]);
            }
        }
#pragma unroll
        for (int q = 0; q < 32; q++) s->Msu[wid][lane * MSPITCH + q] = Macc[q];
    }
    s->fs[wid][lane] = fsum;
    if (lane == 0) s->pflag[wid] = any ? 1 : 0;
    __syncthreads();

    // ================= phase B: [8 x 2048] @ [2048 x 32] ===================
    // warp wid owns channels 4*wid .. 4*wid+3, split into 8 chunks of 32 rows
    u64 acc2[NWB];
#pragma unroll
    for (int q = 0; q < NWB; q++) acc2[q] = 0ull;

    for (int cc = 0; cc < 8; cc++) {
        int c   = 4 * wid + (cc >> 1);
        int j0  = (cc & 1) * 32;
        int jb2 = (cc & 1) * 16;
        u64 wq[16];
        const float* w2base = W2 + (size_t)j0 * (CIN * COUT) + c * COUT + lane;
#pragma unroll
        for (int q = 0; q < 16; q++) {
            float w0 = w2base[(2 * q) * (CIN * COUT)];
            float w1 = w2base[(2 * q + 1) * (CIN * COUT)];
            wq[q] = pack2(w0, w1);
        }
#pragma unroll
        for (int pp = 0; pp < NWB; pp++) {
            if (!s->pflag[pp]) continue;           // warp-uniform skip
            const ulonglong2* mp = (const ulonglong2*)&s->Msu[pp][c * MSPITCH + jb2];
#pragma unroll
            for (int q2 = 0; q2 < 8; q2++) {
                ulonglong2 m = mp[q2];             // broadcast LDS.128
                FMA2(acc2[pp], m.x, wq[2 * q2],     acc2[pp]);
                FMA2(acc2[pp], m.y, wq[2 * q2 + 1], acc2[pp]);
            }
        }
    }
#pragma unroll
    for (int pp = 0; pp < NWB; pp++) {
        float lo, hi;
        unpack2(acc2[pp], lo, hi);
        s->u.red[wid][pp][lane] = lo + hi;
    }
    __syncthreads();

    // ================= epilogue: warp wid finalizes its position ===========
    float o = 0.0f;
#pragma unroll
    for (int w = 0; w < NWB; w++) o += s->u.red[w][wid][lane];

    const float4* fs4 = (const float4*)&s->fs[wid][0];
    const float4* ff4 = (const float4*)&s->ff[wid][0];
#pragma unroll
    for (int q = 0; q < CIN / 4; q++) {
        float4 a  = fs4[q];
        float4 cf = ff4[q];
        o += a.x  * s->b2s[(q * 4 + 0) * 32 + lane];
        o += a.y  * s->b2s[(q * 4 + 1) * 32 + lane];
        o += a.z  * s->b2s[(q * 4 + 2) * 32 + lane];
        o += a.w  * s->b2s[(q * 4 + 3) * 32 + lane];
        o += cf.x * s->wsk[(q * 4 + 0) * 32 + lane];
        o += cf.y * s->wsk[(q * 4 + 1) * 32 + lane];
        o += cf.z * s->wsk[(q * 4 + 2) * 32 + lane];
        o += cf.w * s->wsk[(q * 4 + 3) * 32 + lane];
    }
    o += s->bsk[lane];

    out[(size_t)p * COUT + lane] = o;

    atomicAdd(&s->ssum[lane], o);
    atomicAdd(&s->ssq[lane], o * o);
    __syncthreads();
    if (tid < COUT) {
        atomicAdd(&g_stats[tid],        (double)s->ssum[tid]);
        atomicAdd(&g_stats[COUT + tid], (double)s->ssq[tid]);
    }
}

// ---------------------------------------------------------------------------
// K3: LayerNorm finalize; per-channel scale/bias once per block; 2 float4/thr.
// Last-arriving block re-zeros g_stats for the next graph replay.
// ---------------------------------------------------------------------------
__global__ void k3(float* __restrict__ out,
                   const float* __restrict__ gamma,
                   const float* __restrict__ beta) {
    __shared__ float sc[COUT], sb[COUT];
    int tid = threadIdx.x;
    if (tid < COUT) {
        double n = (double)NPOS;
        double mean = g_stats[tid] / n;
        double var  = g_stats[COUT + tid] / n - mean * mean;
        float rstd = rsqrtf((float)var + EPSV);
        float g = gamma[tid] * rstd;
        sc[tid] = g;
        sb[tid] = beta[tid] - g * (float)mean;
    }
    __syncthreads();

#pragma unroll
    for (int rep = 0; rep < 2; rep++) {
        int e4 = (blockIdx.x * 2 + rep) * blockDim.x + tid;
        if (e4 < NPOS * COUT / 4) {
            int o0 = (e4 * 4) & (COUT - 1);
            float4 v = ((const float4*)out)[e4];
            v.x = v.x * sc[o0]     + sb[o0];
            v.y = v.y * sc[o0 + 1] + sb[o0 + 1];
            v.z = v.z * sc[o0 + 2] + sb[o0 + 2];
            v.w = v.w * sc[o0 + 3] + sb[o0 + 3];
            ((float4*)out)[e4] = v;
        }
    }
    __syncthreads();
    if (tid == 0) {
        __threadfence();
        int old = atomicAdd(&g_sync, 1);
        if (old == (int)gridDim.x - 1) {
            for (int i = 0; i < 2 * COUT; i++) g_stats[i] = 0.0;
            __threadfence();
            g_sync = 0;
        }
    }
}

// ---------------------------------------------------------------------------
extern "C" void kernel_launch(void* const* d_in, const int* in_sizes, int n_in,
                              void* d_out, int out_size) {
    const float* times    = (const float*)d_in[0];
    const float* features = (const float*)d_in[1];
    const void*  mask     = d_in[2];
    const float* W1    = (const float*)d_in[3];
    const float* b1    = (const float*)d_in[4];
    const float* W2    = (const float*)d_in[5];
    const float* b2    = (const float*)d_in[6];
    const float* Wskip = (const float*)d_in[7];
    const float* bskip = (const float*)d_in[8];
    const float* gamma = (const float*)d_in[9];
    const float* beta  = (const float*)d_in[10];
    float* out = (float*)d_out;

    cudaFuncSetAttribute(kfused, cudaFuncAttributeMaxDynamicSharedMemorySize,
                         (int)sizeof(SmemT));

    kfused<<<NBLK, THREADS, sizeof(SmemT)>>>(times, features, mask, W1, b1,
                                             W2, b2, Wskip, bskip, out);
    k3<<<(NPOS * COUT / 4 + 511) / 512, 256>>>(out, gamma, beta);
}

// round 7
// speedup vs baseline: 1.5896x; 1.5896x over previous
#include <cuda_runtime.h>
#include <math.h>

#define BS 4
#define LEN 2048
#define CIN 32
#define COUT 32
#define HIDDIM 64
#define KTAP 8
#define PADL 7
#define NPOS (BS * LEN)
#define RDIM (CIN * HIDDIM)      // 2048
#define EPSV 1e-5f
#define NWB 16                    // positions / warps per block
#define THREADS 512
#define NBLK (NPOS / NWB)         // 512
#define MSPITCH 34                // u64 pitch per channel

typedef unsigned long long u64;

__device__ double g_stats[2 * COUT];
__device__ int    g_sync;

// ---- register-pure packed helpers ----
#define FMA2(d, a, b, c) \
    asm("fma.rn.f32x2 %0, %1, %2, %3;" : "=l"(d) : "l"(a), "l"(b), "l"(c))

__device__ __forceinline__ u64 pack2(float x, float y) {
    u64 d; asm("mov.b64 %0, {%1, %2};" : "=l"(d) : "f"(x), "f"(y)); return d;
}
__device__ __forceinline__ u64 packdup(float x) {
    u64 d; asm("mov.b64 %0, {%1, %1};" : "=l"(d) : "f"(x)); return d;
}
__device__ __forceinline__ void unpack2(u64 v, float& x, float& y) {
    asm("mov.b64 {%0, %1}, %2;" : "=f"(x), "=f"(y) : "l"(v));
}

// mask dtype hedge (byte 1 nonzero <=> 1-byte storage; else 4-byte words)
__device__ __forceinline__ bool mask_at(const void* m, int idx, bool byte_mode) {
    if (byte_mode) return ((const unsigned char*)m)[idx] != 0;
    return ((const unsigned int*)m)[idx] != 0u;
}

struct SmemT {
    float W1s[CIN * HIDDIM];      // 8KB
    float b1s[HIDDIM];
    float b2s[CIN * COUT];        // 4KB
    float wsk[CIN * COUT];        // 4KB
    float bsk[COUT];
    float ff[NWB][CIN];           // 2KB
    float fs[NWB][CIN];           // 2KB
    float ssum[COUT], ssq[COUT];
    int   pflag[NWB];
    union alignas(16) {
        struct {
            float teu[NWB][CIN][KTAP];    // 16KB
            float hb[NWB][KTAP][HIDDIM];  // 32KB
        } a;
        float red[NWB][NWB][COUT];        // 32KB
    } u;
    u64 Msu[NWB][CIN * MSPITCH];  // 136KB
};

// load one chunk's W2 pair-registers: chunk cc of warp wid, output lane o
__device__ __forceinline__ void load_wq(const float* __restrict__ W2,
                                        int wid, int lane, int cc, u64* wq) {
    int c  = 2 * wid + (cc >> 1);
    int j0 = (cc & 1) * 32;
    const float* w2base = W2 + (size_t)j0 * (CIN * COUT) + c * COUT + lane;
#pragma unroll
    for (int q = 0; q < 16; q++) {
        float w0 = w2base[(2 * q) * (CIN * COUT)];
        float w1 = w2base[(2 * q + 1) * (CIN * COUT)];
        wq[q] = pack2(w0, w1);
    }
}

__global__ __launch_bounds__(THREADS, 1)
void kfused(const float* __restrict__ times,
            const float* __restrict__ features,
            const void*  __restrict__ mask,
            const float* __restrict__ W1,
            const float* __restrict__ b1,
            const float* __restrict__ W2,
            const float* __restrict__ b2,
            const float* __restrict__ Wskip,
            const float* __restrict__ bskip,
            float* __restrict__ out) {
    extern __shared__ char smem_raw[];
    SmemT* s = (SmemT*)smem_raw;

    int tid  = threadIdx.x;
    int wid  = tid >> 5;
    int lane = tid & 31;

    // ---- stage constants ----
    for (int i = tid; i < CIN * HIDDIM; i += THREADS) s->W1s[i] = W1[i];
    for (int i = tid; i < CIN * COUT; i += THREADS) {
        s->b2s[i] = b2[i];
        s->wsk[i] = Wskip[i];
    }
    if (tid < HIDDIM) s->b1s[tid] = b1[tid];
    if (tid < COUT) {
        s->bsk[tid]  = bskip[tid];
        s->ssum[tid] = 0.0f;
        s->ssq[tid]  = 0.0f;
    }
    __syncthreads();

    // ================= phase A: build M row (warp per position) ============
    int p = blockIdx.x * NWB + wid;
    int b = p >> 11;
    int t = p & (LEN - 1);

    bool byte_mode = ((const unsigned char*)mask)[1] != 0;
    bool mask_t = mask_at(mask, p, byte_mode);
    float t_here = times[p];

    s->ff[wid][lane] = features[(size_t)p * CIN + lane];

    unsigned vmask = 0;
#pragma unroll
    for (int k = 0; k < KTAP; k++) {
        int idx = t - PADL + k;
        bool dm = mask_t && (idx >= 0);
        if (dm) dm = mask_at(mask, b * LEN + idx, byte_mode);
        if (dm) vmask |= (1u << k);
    }
    bool any = (vmask != 0);
    float fsum = 0.0f;

    if (any) {
        // --- te for all taps (lane = channel i) ---
        float inv_pos = __expf(-(float)(lane >> 1) * (9.210340371976184f / 16.0f));
        float phase   = (lane & 1) ? 1.5707963267948966f : 0.0f;
        float fk[KTAP];
#pragma unroll
        for (int k = 0; k < KTAP; k++) {
            int idx = t - PADL + k;
            float te = 0.0f;
            fk[k] = 0.0f;
            if ((vmask >> k) & 1) {
                float dt = t_here - times[b * LEN + idx];
                te = __sinf(dt * inv_pos + phase);
                fk[k] = features[(size_t)(b * LEN + idx) * CIN + lane];
            }
            s->u.a.teu[wid][lane][k] = te;
            fsum += fk[k];
        }
        __syncwarp();

        // --- h for all taps, i-outer (lane = j; also j+32) ---
        u64 hh[4][2];
#pragma unroll
        for (int k2 = 0; k2 < 4; k2++) {
            hh[k2][0] = packdup(s->b1s[lane]);
            hh[k2][1] = packdup(s->b1s[lane + 32]);
        }
#pragma unroll
        for (int i = 0; i < CIN; i++) {
            u64 w0 = packdup(s->W1s[i * HIDDIM + lane]);
            u64 w1 = packdup(s->W1s[i * HIDDIM + lane + 32]);
#pragma unroll
            for (int k2 = 0; k2 < 4; k2++) {
                u64 tp = *(const u64*)&s->u.a.teu[wid][i][2 * k2];  // bcast
                FMA2(hh[k2][0], tp, w0, hh[k2][0]);
                FMA2(hh[k2][1], tp, w1, hh[k2][1]);
            }
        }
#pragma unroll
        for (int k2 = 0; k2 < 4; k2++) {
            float a0, c0, a1, c1;
            unpack2(hh[k2][0], a0, c0);
            unpack2(hh[k2][1], a1, c1);
            s->u.a.hb[wid][2 * k2][lane]          = fmaxf(a0, 0.0f);
            s->u.a.hb[wid][2 * k2 + 1][lane]      = fmaxf(c0, 0.0f);
            s->u.a.hb[wid][2 * k2][lane + 32]     = fmaxf(a1, 0.0f);
            s->u.a.hb[wid][2 * k2 + 1][lane + 32] = fmaxf(c1, 0.0f);
        }
        __syncwarp();

        // --- M update (lane = channel) ---
        u64 Macc[32];
#pragma unroll
        for (int q = 0; q < 32; q++) Macc[q] = 0ull;
#pragma unroll
        for (int k = 0; k < KTAP; k++) {
            if (!((vmask >> k) & 1)) continue;     // warp-uniform
            u64 f2 = packdup(fk[k]);
            const ulonglong2* hp2 = (const ulonglong2*)&s->u.a.hb[wid][k][0];
#pragma unroll
            for (int q2 = 0; q2 < 16; q2++) {
                ulonglong2 hp = hp2[q2];           // broadcast LDS.128
                FMA2(Macc[2 * q2],     f2, hp.x, Macc[2 * q2]);
                FMA2(Macc[2 * q2 + 1], f2, hp.y, Macc[2 * q2 + 1]);
            }
        }
#pragma unroll
        for (int q = 0; q < 32; q++) s->Msu[wid][lane * MSPITCH + q] = Macc[q];
    }
    s->fs[wid][lane] = fsum;
    if (lane == 0) s->pflag[wid] = any ? 1 : 0;

    // prefetch chunk 0's W2 strip — latency hidden by the barrier wait
    u64 wq[16];
    load_wq(W2, wid, lane, 0, wq);
    __syncthreads();

    // ================= phase B: [16 x 2048] @ [2048 x 32] ==================
    // dual accumulators per position: even/odd j-pair chains (2x ILP)
    u64 accx[NWB], accy[NWB];
#pragma unroll
    for (int q = 0; q < NWB; q++) { accx[q] = 0ull; accy[q] = 0ull; }

    for (int cc = 0; cc < 4; cc++) {
        int c   = 2 * wid + (cc >> 1);
        int jb2 = (cc & 1) * 16;
#pragma unroll
        for (int pp = 0; pp < NWB; pp++) {
            if (!s->pflag[pp]) continue;           // warp-uniform skip
            const ulonglong2* mp = (const ulonglong2*)&s->Msu[pp][c * MSPITCH + jb2];
#pragma unroll
            for (int q2 = 0; q2 < 8; q2++) {
                ulonglong2 m = mp[q2];             // broadcast LDS.128
                FMA2(accx[pp], m.x, wq[2 * q2],     accx[pp]);
                FMA2(accy[pp], m.y, wq[2 * q2 + 1], accy[pp]);
            }
        }
        if (cc < 3) load_wq(W2, wid, lane, cc + 1, wq);
    }
#pragma unroll
    for (int pp = 0; pp < NWB; pp++) {
        float xl, xh, yl, yh;
        unpack2(accx[pp], xl, xh);
        unpack2(accy[pp], yl, yh);
        s->u.red[wid][pp][lane] = (xl + yl) + (xh + yh);
    }
    __syncthreads();

    // ================= epilogue: warp wid finalizes its position ===========
    float o = 0.0f;
#pragma unroll
    for (int w = 0; w < NWB; w++) o += s->u.red[w][wid][lane];

    const float4* fs4 = (const float4*)&s->fs[wid][0];
    const float4* ff4 = (const float4*)&s->ff[wid][0];
#pragma unroll
    for (int q = 0; q < CIN / 4; q++) {
        float4 a  = fs4[q];
        float4 cf = ff4[q];
        o += a.x  * s->b2s[(q * 4 + 0) * 32 + lane];
        o += a.y  * s->b2s[(q * 4 + 1) * 32 + lane];
        o += a.z  * s->b2s[(q * 4 + 2) * 32 + lane];
        o += a.w  * s->b2s[(q * 4 + 3) * 32 + lane];
        o += cf.x * s->wsk[(q * 4 + 0) * 32 + lane];
        o += cf.y * s->wsk[(q * 4 + 1) * 32 + lane];
        o += cf.z * s->wsk[(q * 4 + 2) * 32 + lane];
        o += cf.w * s->wsk[(q * 4 + 3) * 32 + lane];
    }
    o += s->bsk[lane];

    out[(size_t)p * COUT + lane] = o;

    atomicAdd(&s->ssum[lane], o);
    atomicAdd(&s->ssq[lane], o * o);
    __syncthreads();
    if (tid < COUT) {
        atomicAdd(&g_stats[tid],        (double)s->ssum[tid]);
        atomicAdd(&g_stats[COUT + tid], (double)s->ssq[tid]);
    }
}

// ---------------------------------------------------------------------------
// K3: LayerNorm finalize; per-channel scale/bias once per block.
// Last-arriving block re-zeros g_stats for the next graph replay.
// ---------------------------------------------------------------------------
__global__ void k3(float* __restrict__ out,
                   const float* __restrict__ gamma,
                   const float* __restrict__ beta) {
    __shared__ float sc[COUT], sb[COUT];
    int tid = threadIdx.x;
    if (tid < COUT) {
        double n = (double)NPOS;
        double mean = g_stats[tid] / n;
        double var  = g_stats[COUT + tid] / n - mean * mean;
        float rstd = rsqrtf((float)var + EPSV);
        float g = gamma[tid] * rstd;
        sc[tid] = g;
        sb[tid] = beta[tid] - g * (float)mean;
    }
    __syncthreads();

    int e4 = blockIdx.x * blockDim.x + tid;
    if (e4 < NPOS * COUT / 4) {
        int o0 = (e4 * 4) & (COUT - 1);
        float4 v = ((const float4*)out)[e4];
        v.x = v.x * sc[o0]     + sb[o0];
        v.y = v.y * sc[o0 + 1] + sb[o0 + 1];
        v.z = v.z * sc[o0 + 2] + sb[o0 + 2];
        v.w = v.w * sc[o0 + 3] + sb[o0 + 3];
        ((float4*)out)[e4] = v;
    }
    __syncthreads();
    if (tid == 0) {
        __threadfence();
        int old = atomicAdd(&g_sync, 1);
        if (old == (int)gridDim.x - 1) {
            for (int i = 0; i < 2 * COUT; i++) g_stats[i] = 0.0;
            __threadfence();
            g_sync = 0;
        }
    }
}

// ---------------------------------------------------------------------------
extern "C" void kernel_launch(void* const* d_in, const int* in_sizes, int n_in,
                              void* d_out, int out_size) {
    const float* times    = (const float*)d_in[0];
    const float* features = (const float*)d_in[1];
    const void*  mask     = d_in[2];
    const float* W1    = (const float*)d_in[3];
    const float* b1    = (const float*)d_in[4];
    const float* W2    = (const float*)d_in[5];
    const float* b2    = (const float*)d_in[6];
    const float* Wskip = (const float*)d_in[7];
    const float* bskip = (const float*)d_in[8];
    const float* gamma = (const float*)d_in[9];
    const float* beta  = (const float*)d_in[10];
    float* out = (float*)d_out;

    cudaFuncSetAttribute(kfused, cudaFuncAttributeMaxDynamicSharedMemorySize,
                         (int)sizeof(SmemT));

    kfused<<<NBLK, THREADS, sizeof(SmemT)>>>(times, features, mask, W1, b1,
                                             W2, b2, Wskip, bskip, out);
    k3<<<(NPOS * COUT / 4 + 255) / 256, 256>>>(out, gamma, beta);
}